// round 14
// baseline (speedup 1.0000x reference)
#include <cuda_runtime.h>
#include <math.h>

typedef unsigned long long ull;

// Problem constants
#define BATCH 64
#define L0 128
#define C0 16
#define KW 5
#define C1 128
#define C2 1024
#define L2N 120
#define C3 8192
#define L3 116
#define AD 2

// k_back decomposition: unit = (tblk, g8) owned by ONE warp.
// lane = (group-local gl = lane>>2 in [0,8), filter-pair fp = lane&3)
#define TT 4
#define NTBLK (L3 / TT)          // 29
#define NG8 (C2 / 8)             // 128
#define NU (NTBLK * NG8)         // 3712 units
#define BPT 8                    // batches per task
#define NTASK (NU * (BATCH/BPT)) // 29696
#define GRID_BACK 444            // 3 CTAs/SM resident
#define NWARPS (GRID_BACK * 8)   // 3552
#define TPW (NTASK / NWARPS)     // 8
#define TREM (NTASK % NWARPS)    // 1280

// k_front tiling
#define FROWS 6                  // y2 rows per CTA
#define FY1 (FROWS + KW - 1)     // 10 y1 rows

// Scratch (device globals; no allocation)
__device__ float g_y2[(size_t)BATCH * L2N * C2];        // ~31.5 MB (L2-resident)
__device__ float g_part2[(size_t)BATCH * NU * 8 * AD];  // 15.2 MB partials

// ---- f32x2 packed helpers -------------------------------------------------
// Only the FMA/ADD go through asm (no C path). All packing/unpacking is done
// via unions so ptxas can place values directly in register pairs (no MOVs).
union P2 { ull u; float2 f; };

__device__ __forceinline__ ull ffma2(ull a, ull b, ull c) {
    ull d;
    asm("fma.rn.f32x2 %0, %1, %2, %3;" : "=l"(d) : "l"(a), "l"(b), "l"(c));
    return d;
}
__device__ __forceinline__ ull add2(ull a, ull b) {
    ull d;
    asm("add.rn.f32x2 %0, %1, %2;" : "=l"(d) : "l"(a), "l"(b));
    return d;
}
__device__ __forceinline__ ull dup2(float v) {
    P2 x; x.f.x = v; x.f.y = v; return x.u;
}
__device__ __forceinline__ ull mk2(float lo, float hi) {
    P2 x; x.f.x = lo; x.f.y = hi; return x.u;
}
__device__ __forceinline__ ull relu2(ull v) {
    P2 x; x.u = v;
    x.f.x = fmaxf(x.f.x, 0.f);
    x.f.y = fmaxf(x.f.y, 0.f);
    return x.u;
}
__device__ __forceinline__ float hadd2(ull v) {
    P2 x; x.u = v;
    return x.f.x + x.f.y;
}

// ---------------------------------------------------------------------------
// Kernel 1: blocks 1+2. grid (64, 20), block 256. 6 y2 rows per CTA.
// Phase 1 uses a sliding state window: 9 loads per thread instead of 25.
// ---------------------------------------------------------------------------
__global__ __launch_bounds__(256) void k_front(
    const float* __restrict__ state, const float* __restrict__ k1,
    const float* __restrict__ b1, const float* __restrict__ k2,
    const float* __restrict__ b2)
{
    __shared__ float s_y1[FY1 * C1];   // 5 KB
    const int b   = blockIdx.x;
    const int ty  = blockIdx.y;
    const int tid = threadIdx.x;
    const int t0  = ty * FROWS;        // y2 rows [t0, t0+FROWS)
    const float* st = state + (size_t)b * L0 * C0;

    // ---- y1 rows: thread (h, c1) computes rows h*5 .. h*5+4, sliding ----
    {
        const int c1 = tid & (C1 - 1);
        const int h  = tid >> 7;        // 0 or 1
        const int g1 = c1 >> 3;
        float kr[KW];
        const float bb = __ldg(&b1[c1]);
        #pragma unroll
        for (int k = 0; k < KW; k++) kr[k] = __ldg(&k1[k * C1 + c1]);

        const float* sp = st + (t0 + h * 5) * C0 + g1;
        float x0 = __ldg(sp + 0 * C0);
        float x1 = __ldg(sp + 1 * C0);
        float x2 = __ldg(sp + 2 * C0);
        float x3 = __ldg(sp + 3 * C0);
        #pragma unroll
        for (int i = 0; i < 5; i++) {
            const float x4 = __ldg(sp + (i + 4) * C0);
            float z = bb;
            z = fmaf(x0, kr[0], z);
            z = fmaf(x1, kr[1], z);
            z = fmaf(x2, kr[2], z);
            z = fmaf(x3, kr[3], z);
            z = fmaf(x4, kr[4], z);
            s_y1[(h * 5 + i) * C1 + c1] = fmaxf(z, 0.f);
            x0 = x1; x1 = x2; x2 = x3; x3 = x4;
        }
    }
    __syncthreads();

    // ---- y2 rows t0..t0+FROWS-1, sliding window ----
    #pragma unroll
    for (int q = 0; q < 4; q++) {
        const int c2 = tid + q * 256;
        const int g2 = c2 >> 3;
        float kr[KW];
        const float bb = __ldg(&b2[c2]);
        #pragma unroll
        for (int k = 0; k < KW; k++) kr[k] = __ldg(&k2[k * C2 + c2]);
        float* yout = g_y2 + ((size_t)b * L2N + t0) * C2 + c2;
        float w0 = s_y1[0 * C1 + g2];
        float w1 = s_y1[1 * C1 + g2];
        float w2 = s_y1[2 * C1 + g2];
        float w3 = s_y1[3 * C1 + g2];
        #pragma unroll
        for (int i = 0; i < FROWS; i++) {
            const float w4 = s_y1[(i + 4) * C1 + g2];
            float z = bb;
            z = fmaf(w0, kr[0], z);
            z = fmaf(w1, kr[1], z);
            z = fmaf(w2, kr[2], z);
            z = fmaf(w3, kr[3], z);
            z = fmaf(w4, kr[4], z);
            yout[(size_t)i * C2] = fmaxf(z, 0.f);
            w0 = w1; w1 = w2; w2 = w3; w3 = w4;
        }
    }
}

// ---------------------------------------------------------------------------
// Kernel 2: fused block3 + dense. Filter-pair per lane, union-based packing
// (in-place relu, no asm MOV boundaries), full deferred acc[8], quad-only
// reduction, float2 store epilogue. grid 444, block 256, 3 CTAs/SM.
// ---------------------------------------------------------------------------
__global__ __launch_bounds__(256, 3) void k_back(
    const float* __restrict__ k3, const float* __restrict__ b3,
    const float* __restrict__ W)
{
    const int tid  = threadIdx.x;
    const int lane = tid & 31;
    const int wid  = tid >> 5;
    const int wg   = blockIdx.x * 8 + wid;

    const int cnt   = TPW + (wg < TREM);
    const int start = wg * TPW + (wg < TREM ? wg : TREM);
    const int end   = start + cnt;

    const int fp = lane & 3;     // filter pair within group
    const int gl = lane >> 2;    // group within g8 block

    int uprev = -1;
    ull kr2[KW];       // conv weights, packed filter pair
    ull br2 = 0;       // bias pair
    ull wr2[TT][AD];   // dense weights

    for (int j = start; j < end; j++) {
        const int u    = j >> 3, bc = j & 7;
        const int tblk = u % NTBLK, g8 = u / NTBLK;
        const int g3   = g8 * 8 + gl;
        const int t30  = tblk * TT;

        if (u != uprev) {
            uprev = u;
            const int c = g3 * 8 + fp * 2;   // first of 2 channels this lane owns
            #pragma unroll
            for (int k = 0; k < KW; k++)
                kr2[k] = __ldg((const ull*)(k3 + k * C3 + c));
            br2 = __ldg((const ull*)(b3 + c));
            #pragma unroll
            for (int i = 0; i < TT; i++) {
                float4 q = __ldg((const float4*)(W + ((size_t)(t30 + i) * C3 + c) * AD));
                wr2[i][0] = mk2(q.x, q.z);   // action 0: (w[c], w[c+1])
                wr2[i][1] = mk2(q.y, q.w);   // action 1
            }
        }

        const float* yp = g_y2 + ((size_t)(bc * BPT) * L2N + t30) * C2 + g3;
        ull acc[BPT];

        #pragma unroll
        for (int bb = 0; bb < BPT; bb++) {
            ull yv2[TT + 4];
            #pragma unroll
            for (int r = 0; r < TT + 4; r++)
                yv2[r] = dup2(__ldg(yp + (size_t)r * C2));
            yp += (size_t)L2N * C2;   // next batch

            ull a0p = 0ull, a1p = 0ull;
            #pragma unroll
            for (int i = 0; i < TT; i++) {
                ull z2 = br2;
                #pragma unroll
                for (int k = 0; k < KW; k++)
                    z2 = ffma2(yv2[i + k], kr2[k], z2);
                const ull v2 = relu2(z2);
                a0p = ffma2(v2, wr2[i][0], a0p);
                a1p = ffma2(v2, wr2[i][1], a1p);
            }
            // fold filter-pair halves -> packed (act0, act1)
            acc[bb] = mk2(hadd2(a0p), hadd2(a1p));
        }

        // ---- deferred quad reduction (2 interleaved shuffle steps) ----
        #pragma unroll
        for (int off = 1; off <= 2; off <<= 1) {
            #pragma unroll
            for (int bb = 0; bb < BPT; bb++)
                acc[bb] = add2(acc[bb], __shfl_xor_sync(0xffffffffu, acc[bb], off));
        }
        if (fp == 0) {
            #pragma unroll
            for (int bb = 0; bb < BPT; bb++) {
                const int b = bc * BPT + bb;
                P2 x; x.u = acc[bb];
                *(float2*)(g_part2 + (((size_t)b * NU + u) * 8 + gl) * AD) = x.f;
            }
        }
    }
}

// ---------------------------------------------------------------------------
// Kernel 3: per-batch reduce of NU*8 float2 partials, bias + tanh.
// grid 64 (one block per batch), block 256.
// ---------------------------------------------------------------------------
__global__ __launch_bounds__(256) void k_out(
    const float* __restrict__ bd, float* __restrict__ out)
{
    __shared__ float s0[8], s1[8];
    const int b   = blockIdx.x;
    const int tid = threadIdx.x;
    const float2* p = (const float2*)(g_part2 + (size_t)b * NU * 8 * AD);
    float v0 = 0.f, v1 = 0.f;
    for (int i = tid; i < NU * 8; i += 256) {
        float2 q = __ldg(p + i);
        v0 += q.x; v1 += q.y;
    }
    #pragma unroll
    for (int off = 16; off; off >>= 1) {
        v0 += __shfl_xor_sync(0xffffffffu, v0, off);
        v1 += __shfl_xor_sync(0xffffffffu, v1, off);
    }
    if ((tid & 31) == 0) { s0[tid >> 5] = v0; s1[tid >> 5] = v1; }
    __syncthreads();
    if (tid == 0) {
        float a0 = 0.f, a1 = 0.f;
        #pragma unroll
        for (int w = 0; w < 8; w++) { a0 += s0[w]; a1 += s1[w]; }
        out[b * AD + 0] = tanhf(a0 + bd[0]);
        out[b * AD + 1] = tanhf(a1 + bd[1]);
    }
}

extern "C" void kernel_launch(void* const* d_in, const int* in_sizes, int n_in,
                              void* d_out, int out_size) {
    (void)in_sizes; (void)n_in; (void)out_size;
    const float* state = (const float*)d_in[0];
    const float* k1    = (const float*)d_in[1];
    const float* b1    = (const float*)d_in[2];
    const float* k2    = (const float*)d_in[3];
    const float* b2    = (const float*)d_in[4];
    const float* k3    = (const float*)d_in[5];
    const float* b3    = (const float*)d_in[6];
    const float* W     = (const float*)d_in[7];
    const float* bd    = (const float*)d_in[8];
    float* out = (float*)d_out;

    k_front<<<dim3(BATCH, L2N / FROWS), 256>>>(state, k1, b1, k2, b2);
    k_back <<<GRID_BACK, 256>>>(k3, b3, W);
    k_out  <<<BATCH, 256>>>(bd, out);
}

// round 15
// speedup vs baseline: 1.1952x; 1.1952x over previous
#include <cuda_runtime.h>
#include <math.h>

typedef unsigned long long ull;

// Problem constants
#define BATCH 64
#define L0 128
#define C0 16
#define KW 5
#define C1 128
#define C2 1024
#define L2N 120
#define C3 8192
#define L3 116
#define AD 2

// k_back decomposition: unit = (tblk, g8) owned by ONE warp.
// lane = (group-local gl = lane>>2 in [0,8), filter-pair fp = lane&3)
#define TT 4
#define NTBLK (L3 / TT)          // 29
#define NG8 (C2 / 8)             // 128
#define NU (NTBLK * NG8)         // 3712 units
#define BPT 8                    // batches per task
#define NTASK (NU * (BATCH/BPT)) // 29696
#define GRID_BACK 444            // 3 CTAs/SM resident
#define NWARPS (GRID_BACK * 8)   // 3552
#define TPW (NTASK / NWARPS)     // 8
#define TREM (NTASK % NWARPS)    // 1280

// k_front tiling (R7 measured-best: 9.47us)
#define FROWS 8                  // y2 rows per CTA
#define FY1 (FROWS + KW - 1)     // 12 y1 rows

// Scratch (device globals; no allocation)
__device__ float g_y2[(size_t)BATCH * L2N * C2];        // ~31.5 MB (L2-resident)
__device__ float g_part2[(size_t)BATCH * NU * 8 * AD];  // 15.2 MB partials

// ---- f32x2 packed helpers (asm pack: measured-best form) -------------------
__device__ __forceinline__ ull ffma2(ull a, ull b, ull c) {
    ull d;
    asm("fma.rn.f32x2 %0, %1, %2, %3;" : "=l"(d) : "l"(a), "l"(b), "l"(c));
    return d;
}
__device__ __forceinline__ ull add2(ull a, ull b) {
    ull d;
    asm("add.rn.f32x2 %0, %1, %2;" : "=l"(d) : "l"(a), "l"(b));
    return d;
}
__device__ __forceinline__ ull pack2(float lo, float hi) {
    ull d;
    asm("mov.b64 %0, {%1, %2};" : "=l"(d) : "f"(lo), "f"(hi));
    return d;
}
__device__ __forceinline__ void unpack2(ull v, float& lo, float& hi) {
    asm("mov.b64 {%0, %1}, %2;" : "=f"(lo), "=f"(hi) : "l"(v));
}

// ---------------------------------------------------------------------------
// Kernel 1: blocks 1+2. grid (64, 15), block 256. 8 y2 rows per CTA.
// (R7 measured-best form)
// ---------------------------------------------------------------------------
__global__ __launch_bounds__(256) void k_front(
    const float* __restrict__ state, const float* __restrict__ k1,
    const float* __restrict__ b1, const float* __restrict__ k2,
    const float* __restrict__ b2)
{
    __shared__ float s_y1[FY1 * C1];   // 6 KB
    const int b   = blockIdx.x;
    const int ty  = blockIdx.y;
    const int tid = threadIdx.x;
    const int t0  = ty * FROWS;        // y2 rows [t0, t0+8)
    const float* st = state + (size_t)b * L0 * C0;

    // ---- y1 rows t0..t0+11 ----
    {
        const int c1 = tid & (C1 - 1);
        const int g1 = c1 >> 3;
        float kr[KW];
        const float bb = b1[c1];
        #pragma unroll
        for (int k = 0; k < KW; k++) kr[k] = k1[k * C1 + c1];
        #pragma unroll
        for (int i = (tid >> 7); i < FY1; i += 2) {
            const int t = t0 + i;
            float z = bb;
            #pragma unroll
            for (int k = 0; k < KW; k++)
                z = fmaf(st[(t + k) * C0 + g1], kr[k], z);
            s_y1[i * C1 + c1] = fmaxf(z, 0.f);
        }
    }
    __syncthreads();

    // ---- y2 rows t0..t0+7, sliding window ----
    #pragma unroll
    for (int q = 0; q < 4; q++) {
        const int c2 = tid + q * 256;
        const int g2 = c2 >> 3;
        float kr[KW];
        const float bb = b2[c2];
        #pragma unroll
        for (int k = 0; k < KW; k++) kr[k] = k2[k * C2 + c2];
        float* yout = g_y2 + ((size_t)b * L2N + t0) * C2 + c2;
        float w0 = s_y1[0 * C1 + g2];
        float w1 = s_y1[1 * C1 + g2];
        float w2 = s_y1[2 * C1 + g2];
        float w3 = s_y1[3 * C1 + g2];
        #pragma unroll
        for (int i = 0; i < FROWS; i++) {
            const float w4 = s_y1[(i + 4) * C1 + g2];
            float z = bb;
            z = fmaf(w0, kr[0], z);
            z = fmaf(w1, kr[1], z);
            z = fmaf(w2, kr[2], z);
            z = fmaf(w3, kr[3], z);
            z = fmaf(w4, kr[4], z);
            yout[(size_t)i * C2] = fmaxf(z, 0.f);
            w0 = w1; w1 = w2; w2 = w3; w3 = w4;
        }
    }
}

// ---------------------------------------------------------------------------
// Kernel 2: fused block3 + dense (R9 measured-best: 34.7us).
// Filter-pair per lane, one-batch-ahead prefetch, half-deferred quad
// reduction, float2 store epilogue. grid 444, block 256, 3 CTAs/SM.
// ---------------------------------------------------------------------------
__global__ __launch_bounds__(256, 3) void k_back(
    const float* __restrict__ k3, const float* __restrict__ b3,
    const float* __restrict__ W)
{
    const int tid  = threadIdx.x;
    const int lane = tid & 31;
    const int wid  = tid >> 5;
    const int wg   = blockIdx.x * 8 + wid;

    const int cnt   = TPW + (wg < TREM);
    const int start = wg * TPW + (wg < TREM ? wg : TREM);
    const int end   = start + cnt;

    const int fp = lane & 3;     // filter pair within group
    const int gl = lane >> 2;    // group within g8 block

    int uprev = -1;
    ull kr2[KW];       // conv weights, packed filter pair
    ull br2 = 0;       // bias pair
    ull wr2[TT][AD];   // dense weights

    for (int j = start; j < end; j++) {
        const int u    = j >> 3, bc = j & 7;
        const int tblk = u % NTBLK, g8 = u / NTBLK;
        const int g3   = g8 * 8 + gl;
        const int t30  = tblk * TT;
        const int c    = g3 * 8 + fp * 2;   // first of 2 channels this lane owns

        if (u != uprev) {
            uprev = u;
            #pragma unroll
            for (int k = 0; k < KW; k++)
                kr2[k] = *(const ull*)(k3 + k * C3 + c);
            br2 = *(const ull*)(b3 + c);
            #pragma unroll
            for (int i = 0; i < TT; i++) {
                float4 q = *(const float4*)(W + ((size_t)(t30 + i) * C3 + c) * AD);
                wr2[i][0] = pack2(q.x, q.z);   // action 0: (w[c], w[c+1])
                wr2[i][1] = pack2(q.y, q.w);   // action 1
            }
        }

        const float* ytask = g_y2 + ((size_t)(bc * BPT) * L2N + t30) * C2 + g3;
        ull acc[BPT / 2];

        // prime: load batch 0 rows
        float yv[TT + 4];
        #pragma unroll
        for (int r = 0; r < TT + 4; r++) yv[r] = ytask[(size_t)r * C2];

        #pragma unroll
        for (int half = 0; half < 2; half++) {
            #pragma unroll
            for (int q = 0; q < BPT / 2; q++) {
                const int bb = half * (BPT / 2) + q;
                // ---- prefetch next batch while computing this one ----
                float yn[TT + 4];
                if (bb + 1 < BPT) {
                    const float* yp = ytask + (size_t)(bb + 1) * L2N * C2;
                    #pragma unroll
                    for (int r = 0; r < TT + 4; r++) yn[r] = yp[(size_t)r * C2];
                }

                ull yv2[TT + 4];
                #pragma unroll
                for (int r = 0; r < TT + 4; r++) yv2[r] = pack2(yv[r], yv[r]);

                ull a0p = 0ull, a1p = 0ull;
                #pragma unroll
                for (int i = 0; i < TT; i++) {
                    ull z2 = br2;
                    #pragma unroll
                    for (int k = 0; k < KW; k++)
                        z2 = ffma2(yv2[i + k], kr2[k], z2);
                    float v0, v1;
                    unpack2(z2, v0, v1);
                    v0 = fmaxf(v0, 0.f);
                    v1 = fmaxf(v1, 0.f);
                    const ull v2 = pack2(v0, v1);
                    a0p = ffma2(v2, wr2[i][0], a0p);
                    a1p = ffma2(v2, wr2[i][1], a1p);
                }
                // fold filter-pair halves -> packed (act0, act1)
                float a0l, a0h, a1l, a1h;
                unpack2(a0p, a0l, a0h);
                unpack2(a1p, a1l, a1h);
                acc[q] = pack2(a0l + a0h, a1l + a1h);

                if (bb + 1 < BPT) {
                    #pragma unroll
                    for (int r = 0; r < TT + 4; r++) yv[r] = yn[r];
                }
            }

            // ---- quad reduction for this half (2 interleaved shuffle steps) ----
            #pragma unroll
            for (int off = 1; off <= 2; off <<= 1) {
                #pragma unroll
                for (int q = 0; q < BPT / 2; q++)
                    acc[q] = add2(acc[q], __shfl_xor_sync(0xffffffffu, acc[q], off));
            }
            if (fp == 0) {
                #pragma unroll
                for (int q = 0; q < BPT / 2; q++) {
                    const int b = bc * BPT + half * (BPT / 2) + q;
                    float r0, r1;
                    unpack2(acc[q], r0, r1);
                    float2 res; res.x = r0; res.y = r1;
                    *(float2*)(g_part2 + (((size_t)b * NU + u) * 8 + gl) * AD) = res;
                }
            }
        }
    }
}

// ---------------------------------------------------------------------------
// Kernel 3: per-batch reduce of NU*8 float2 partials, bias + tanh.
// grid 64 (one block per batch), block 256.
// ---------------------------------------------------------------------------
__global__ __launch_bounds__(256) void k_out(
    const float* __restrict__ bd, float* __restrict__ out)
{
    __shared__ float s0[8], s1[8];
    const int b   = blockIdx.x;
    const int tid = threadIdx.x;
    const float2* p = (const float2*)(g_part2 + (size_t)b * NU * 8 * AD);
    float v0 = 0.f, v1 = 0.f;
    for (int i = tid; i < NU * 8; i += 256) {
        float2 q = p[i];
        v0 += q.x; v1 += q.y;
    }
    #pragma unroll
    for (int off = 16; off; off >>= 1) {
        v0 += __shfl_xor_sync(0xffffffffu, v0, off);
        v1 += __shfl_xor_sync(0xffffffffu, v1, off);
    }
    if ((tid & 31) == 0) { s0[tid >> 5] = v0; s1[tid >> 5] = v1; }
    __syncthreads();
    if (tid == 0) {
        float a0 = 0.f, a1 = 0.f;
        #pragma unroll
        for (int w = 0; w < 8; w++) { a0 += s0[w]; a1 += s1[w]; }
        out[b * AD + 0] = tanhf(a0 + bd[0]);
        out[b * AD + 1] = tanhf(a1 + bd[1]);
    }
}

extern "C" void kernel_launch(void* const* d_in, const int* in_sizes, int n_in,
                              void* d_out, int out_size) {
    (void)in_sizes; (void)n_in; (void)out_size;
    const float* state = (const float*)d_in[0];
    const float* k1    = (const float*)d_in[1];
    const float* b1    = (const float*)d_in[2];
    const float* k2    = (const float*)d_in[3];
    const float* b2    = (const float*)d_in[4];
    const float* k3    = (const float*)d_in[5];
    const float* b3    = (const float*)d_in[6];
    const float* W     = (const float*)d_in[7];
    const float* bd    = (const float*)d_in[8];
    float* out = (float*)d_out;

    k_front<<<dim3(BATCH, L2N / FROWS), 256>>>(state, k1, b1, k2, b2);
    k_back <<<GRID_BACK, 256>>>(k3, b3, W);
    k_out  <<<BATCH, 256>>>(bd, out);
}